// round 1
// baseline (speedup 1.0000x reference)
#include <cuda_runtime.h>

#define NODES_PER_GRAPH 1024
#define TILE 128
#define HDIM 64
#define Y1_STRIDE (HDIM + 1)

// prev node on the per-graph ring
__device__ __forceinline__ int prev_node(int j) {
    return ((j & (NODES_PER_GRAPH - 1)) == 0) ? j + NODES_PER_GRAPH - 1 : j - 1;
}

extern __shared__ float smem[];

__global__ void __launch_bounds__(TILE, 4) gnn_fused(
    const float* __restrict__ x,
    const float* __restrict__ W1, const float* __restrict__ b1,
    const float* __restrict__ W2, const float* __restrict__ b2,
    const float* __restrict__ Wl, const float* __restrict__ bl,
    float* __restrict__ out)
{
    float* sW2 = smem;                     // 64*64
    float* sW1 = sW2 + HDIM * HDIM;        // 3*64
    float* sb1 = sW1 + 3 * HDIM;           // 64
    float* sb2 = sb1 + HDIM;               // 64
    float* sWl = sb2 + HDIM;               // 64*3
    float* y1s = sWl + HDIM * 3;           // (TILE+1) * Y1_STRIDE

    const int t = threadIdx.x;
    const int base = blockIdx.x * TILE;

    // stage weights into shared
    for (int i = t; i < HDIM * HDIM; i += TILE) sW2[i] = W2[i];
    for (int i = t; i < 3 * HDIM; i += TILE)    sW1[i] = W1[i];
    for (int i = t; i < HDIM; i += TILE) { sb1[i] = b1[i]; sb2[i] = b2[i]; }
    for (int i = t; i < HDIM * 3; i += TILE)    sWl[i] = Wl[i];
    __syncthreads();

    // ---- stage 1: y1[r] = relu( 0.5*(x[node]+x[prev]) @ W1 + b1 )
    // buffer row r <-> node (base + r - 1);  row 0 = prev(base) (halo)
    for (int r = t; r < TILE + 1; r += TILE) {
        int node = (r == 0) ? prev_node(base) : (base + r - 1);
        int p = prev_node(node);
        float u0 = 0.5f * (x[3 * node + 0] + x[3 * p + 0]);
        float u1 = 0.5f * (x[3 * node + 1] + x[3 * p + 1]);
        float u2 = 0.5f * (x[3 * node + 2] + x[3 * p + 2]);
        float* row = y1s + r * Y1_STRIDE;
        #pragma unroll
        for (int n = 0; n < HDIM; n++) {
            float v = fmaf(u0, sW1[n],
                      fmaf(u1, sW1[HDIM + n],
                      fmaf(u2, sW1[2 * HDIM + n], sb1[n])));
            row[n] = fmaxf(v, 0.0f);
        }
    }
    __syncthreads();

    // ---- stage 2: acc = 0.5*(y1[cur]+y1[prev]) @ W2 + b2   (dominant GEMV)
    const float* rc = y1s + (t + 1) * Y1_STRIDE;  // node base+t
    const float* rp = y1s + t * Y1_STRIDE;        // prev(base+t)
    float acc[HDIM];
    #pragma unroll
    for (int n = 0; n < HDIM; n++) acc[n] = sb2[n];

    #pragma unroll 4
    for (int k = 0; k < HDIM; k++) {
        float vk = 0.5f * (rc[k] + rp[k]);
        const float4* wrow = reinterpret_cast<const float4*>(sW2 + k * HDIM);
        #pragma unroll
        for (int n4 = 0; n4 < HDIM / 4; n4++) {
            float4 w = wrow[n4];
            acc[4 * n4 + 0] = fmaf(vk, w.x, acc[4 * n4 + 0]);
            acc[4 * n4 + 1] = fmaf(vk, w.y, acc[4 * n4 + 1]);
            acc[4 * n4 + 2] = fmaf(vk, w.z, acc[4 * n4 + 2]);
            acc[4 * n4 + 3] = fmaf(vk, w.w, acc[4 * n4 + 3]);
        }
    }

    // ---- stage 3: out = relu(acc) @ Wl + bl
    float o0 = bl[0], o1 = bl[1], o2 = bl[2];
    #pragma unroll
    for (int n = 0; n < HDIM; n++) {
        float y = fmaxf(acc[n], 0.0f);
        o0 = fmaf(y, sWl[3 * n + 0], o0);
        o1 = fmaf(y, sWl[3 * n + 1], o1);
        o2 = fmaf(y, sWl[3 * n + 2], o2);
    }
    int node = base + t;
    out[3 * node + 0] = o0;
    out[3 * node + 1] = o1;
    out[3 * node + 2] = o2;
}

static const int SMEM_BYTES =
    (HDIM * HDIM + 3 * HDIM + HDIM + HDIM + HDIM * 3 + (TILE + 1) * Y1_STRIDE) * (int)sizeof(float);

extern "C" void kernel_launch(void* const* d_in, const int* in_sizes, int n_in,
                              void* d_out, int out_size) {
    // metadata order: node_index, edge_index, W1, b1, W2, b2, Wl, bl
    const float* x  = (const float*)d_in[0];
    const float* W1 = (const float*)d_in[2];
    const float* b1 = (const float*)d_in[3];
    const float* W2 = (const float*)d_in[4];
    const float* b2 = (const float*)d_in[5];
    const float* Wl = (const float*)d_in[6];
    const float* bl = (const float*)d_in[7];
    float* out = (float*)d_out;

    int N = in_sizes[0] / 3;        // number of nodes
    int grid = N / TILE;

    cudaFuncSetAttribute(gnn_fused, cudaFuncAttributeMaxDynamicSharedMemorySize, SMEM_BYTES);
    gnn_fused<<<grid, TILE, SMEM_BYTES>>>(x, W1, b1, W2, b2, Wl, bl, out);
}

// round 3
// speedup vs baseline: 1.3299x; 1.3299x over previous
#include <cuda_runtime.h>
#include <cstdint>

#define NODES_PER_GRAPH 1024
#define TILE 128
#define HDIM 64
#define AVG_STRIDE 128   // floats per k-row of avgT

// prev node on the per-graph ring
__device__ __forceinline__ int prev_node(int j) {
    return ((j & (NODES_PER_GRAPH - 1)) == 0) ? j + NODES_PER_GRAPH - 1 : j - 1;
}

__device__ __forceinline__ unsigned long long pack2(float lo, float hi) {
    unsigned long long r;
    asm("mov.b64 %0, {%1, %2};" : "=l"(r) : "f"(lo), "f"(hi));
    return r;
}

__device__ __forceinline__ unsigned long long ffma2(unsigned long long a,
                                                    unsigned long long b,
                                                    unsigned long long c) {
    unsigned long long d;
    asm("fma.rn.f32x2 %0, %1, %2, %3;" : "=l"(d) : "l"(a), "l"(b), "l"(c));
    return d;
}

__device__ __forceinline__ void unpack2(unsigned long long v, float& lo, float& hi) {
    asm("mov.b64 {%0, %1}, %2;" : "=f"(lo), "=f"(hi) : "l"(v));
}

extern __shared__ float smem[];

__global__ void __launch_bounds__(TILE, 4) gnn_fused2(
    const float* __restrict__ x,
    const float* __restrict__ W1, const float* __restrict__ b1,
    const float* __restrict__ W2, const float* __restrict__ b2,
    const float* __restrict__ Wl, const float* __restrict__ bl,
    float* __restrict__ out)
{
    float* sW2  = smem;                       // 64*64   = 4096
    float* sW1  = sW2 + HDIM * HDIM;          // 3*64    = 192
    float* sb1  = sW1 + 3 * HDIM;             // 64
    float* sb2  = sb1 + HDIM;                 // 64
    float* sWl  = sb2 + HDIM;                 // 64*3    = 192
    float* avgT = sWl + HDIM * 3;             // 64*128  = 8192  (transposed, pre-averaged)

    const int t    = threadIdx.x;
    const int base = blockIdx.x * TILE;

    // stage weights into shared (FULL strided loops — R2 bug was partial loads here)
    for (int i = t; i < HDIM * HDIM; i += TILE) sW2[i] = W2[i];
    for (int i = t; i < 3 * HDIM; i += TILE)    sW1[i] = W1[i];
    for (int i = t; i < HDIM; i += TILE) { sb1[i] = b1[i]; sb2[i] = b2[i]; }
    for (int i = t; i < HDIM * 3; i += TILE)    sWl[i] = Wl[i];
    __syncthreads();

    // ---- stage 1: each thread computes relu-layer1 for its node m AND prev(m),
    // averages them, stores TRANSPOSED:  avgT[k][t] = 0.5*(y1[m][k] + y1[p][k])
    {
        const int m  = base + t;
        const int p  = prev_node(m);
        const int pp = prev_node(p);
        const float xm0 = x[3*m+0], xm1 = x[3*m+1], xm2 = x[3*m+2];
        const float xp0 = x[3*p+0], xp1 = x[3*p+1], xp2 = x[3*p+2];
        const float xq0 = x[3*pp+0], xq1 = x[3*pp+1], xq2 = x[3*pp+2];
        // averaged inputs for node m and node p (GCN norm = 0.5 on this ring)
        const float um0 = 0.5f*(xm0+xp0), um1 = 0.5f*(xm1+xp1), um2 = 0.5f*(xm2+xp2);
        const float up0 = 0.5f*(xp0+xq0), up1 = 0.5f*(xp1+xq1), up2 = 0.5f*(xp2+xq2);
        #pragma unroll
        for (int k = 0; k < HDIM; k++) {
            float w0 = sW1[k], w1 = sW1[HDIM+k], w2 = sW1[2*HDIM+k], bb = sb1[k];
            float ym = fmaxf(fmaf(um0,w0, fmaf(um1,w1, fmaf(um2,w2, bb))), 0.0f);
            float yp = fmaxf(fmaf(up0,w0, fmaf(up1,w1, fmaf(up2,w2, bb))), 0.0f);
            avgT[k * AVG_STRIDE + t] = 0.5f * (ym + yp);
        }
    }
    __syncthreads();

    // ---- stage 2: y2 = avg @ W2 + b2  as a register-tiled block GEMM.
    // Thread tile: 4 nodes (ng) x 16 cols (cg), packed-f32x2 accumulators.
    const int cg = t & 3;          // col group: cols [cg*16, cg*16+16)
    const int ng = t >> 2;         // node group: local nodes [ng*4, ng*4+4)

    unsigned long long acc[4][8];
    {
        const ulonglong2* bp = reinterpret_cast<const ulonglong2*>(sb2 + cg * 16);
        ulonglong2 b01 = bp[0], b23 = bp[1], b45 = bp[2], b67 = bp[3];
        #pragma unroll
        for (int n = 0; n < 4; n++) {
            acc[n][0] = b01.x; acc[n][1] = b01.y;
            acc[n][2] = b23.x; acc[n][3] = b23.y;
            acc[n][4] = b45.x; acc[n][5] = b45.y;
            acc[n][6] = b67.x; acc[n][7] = b67.y;
        }
    }

    #pragma unroll 4
    for (int k = 0; k < HDIM; k++) {
        float4 yv = *reinterpret_cast<const float4*>(avgT + k * AVG_STRIDE + ng * 4);
        unsigned long long v0 = pack2(yv.x, yv.x);
        unsigned long long v1 = pack2(yv.y, yv.y);
        unsigned long long v2 = pack2(yv.z, yv.z);
        unsigned long long v3 = pack2(yv.w, yv.w);

        const ulonglong2* wp = reinterpret_cast<const ulonglong2*>(sW2 + k * HDIM + cg * 16);
        ulonglong2 wa = wp[0], wb = wp[1], wc = wp[2], wd = wp[3];
        unsigned long long w[8] = { wa.x, wa.y, wb.x, wb.y, wc.x, wc.y, wd.x, wd.y };

        #pragma unroll
        for (int j = 0; j < 8; j++) {
            acc[0][j] = ffma2(v0, w[j], acc[0][j]);
            acc[1][j] = ffma2(v1, w[j], acc[1][j]);
            acc[2][j] = ffma2(v2, w[j], acc[2][j]);
            acc[3][j] = ffma2(v3, w[j], acc[3][j]);
        }
    }

    // ---- stage 3: partial head: o[n][c] = sum over this thread's 16 cols of
    // relu(y2) * Wl, then butterfly-reduce over the 4 col-groups.
    float o[4][3];
    #pragma unroll
    for (int n = 0; n < 4; n++) { o[n][0] = 0.f; o[n][1] = 0.f; o[n][2] = 0.f; }

    #pragma unroll
    for (int j = 0; j < 8; j++) {
        int c0 = cg * 16 + 2 * j;
        float wl00 = sWl[3*c0+0], wl01 = sWl[3*c0+1], wl02 = sWl[3*c0+2];
        float wl10 = sWl[3*c0+3], wl11 = sWl[3*c0+4], wl12 = sWl[3*c0+5];
        #pragma unroll
        for (int n = 0; n < 4; n++) {
            float lo, hi;
            unpack2(acc[n][j], lo, hi);
            lo = fmaxf(lo, 0.0f); hi = fmaxf(hi, 0.0f);
            o[n][0] = fmaf(lo, wl00, fmaf(hi, wl10, o[n][0]));
            o[n][1] = fmaf(lo, wl01, fmaf(hi, wl11, o[n][1]));
            o[n][2] = fmaf(lo, wl02, fmaf(hi, wl12, o[n][2]));
        }
    }

    // reduce across the 4 col-group lanes (t^1, t^2 stay in-warp)
    #pragma unroll
    for (int n = 0; n < 4; n++) {
        #pragma unroll
        for (int c = 0; c < 3; c++) {
            float v = o[n][c];
            v += __shfl_xor_sync(0xffffffffu, v, 1);
            v += __shfl_xor_sync(0xffffffffu, v, 2);
            o[n][c] = v;
        }
    }

    if (cg == 0) {
        float bl0 = bl[0], bl1 = bl[1], bl2 = bl[2];
        #pragma unroll
        for (int n = 0; n < 4; n++) {
            int node = base + ng * 4 + n;
            out[3*node+0] = o[n][0] + bl0;
            out[3*node+1] = o[n][1] + bl1;
            out[3*node+2] = o[n][2] + bl2;
        }
    }
}

static const int SMEM_BYTES =
    (HDIM * HDIM + 3 * HDIM + HDIM + HDIM + HDIM * 3 + HDIM * AVG_STRIDE) * (int)sizeof(float);

extern "C" void kernel_launch(void* const* d_in, const int* in_sizes, int n_in,
                              void* d_out, int out_size) {
    // metadata order: node_index, edge_index, W1, b1, W2, b2, Wl, bl
    const float* x  = (const float*)d_in[0];
    const float* W1 = (const float*)d_in[2];
    const float* b1 = (const float*)d_in[3];
    const float* W2 = (const float*)d_in[4];
    const float* b2 = (const float*)d_in[5];
    const float* Wl = (const float*)d_in[6];
    const float* bl = (const float*)d_in[7];
    float* out = (float*)d_out;

    int N = in_sizes[0] / 3;        // number of nodes
    int grid = N / TILE;

    cudaFuncSetAttribute(gnn_fused2, cudaFuncAttributeMaxDynamicSharedMemorySize, SMEM_BYTES);
    gnn_fused2<<<grid, TILE, SMEM_BYTES>>>(x, W1, b1, W2, b2, Wl, bl, out);
}

// round 5
// speedup vs baseline: 4.8365x; 3.6367x over previous
#include <cuda_runtime.h>
#include <cstdint>

#define NPG  1024
#define TILE 128
#define HD   64

__device__ __forceinline__ int prev_node(int j) {
    return ((j & (NPG - 1)) == 0) ? j + NPG - 1 : j - 1;
}

__device__ __forceinline__ uint32_t f2tf32(float f) {
    uint32_t r;
    asm("cvt.rna.tf32.f32 %0, %1;" : "=r"(r) : "f"(f));
    return r;
}

__device__ __forceinline__ void mma_tf32(float* d, const uint32_t* a, const uint32_t* b) {
    asm volatile(
        "mma.sync.aligned.m16n8k8.row.col.f32.tf32.tf32.f32 "
        "{%0,%1,%2,%3}, {%4,%5,%6,%7}, {%8,%9}, {%0,%1,%2,%3};"
        : "+f"(d[0]), "+f"(d[1]), "+f"(d[2]), "+f"(d[3])
        : "r"(a[0]), "r"(a[1]), "r"(a[2]), "r"(a[3]), "r"(b[0]), "r"(b[1]));
}

__device__ __forceinline__ float dot3(float4 u, float4 w) {
    // w = {w1x, w1y, w1z, b1}
    return fmaf(u.x, w.x, fmaf(u.y, w.y, fmaf(u.z, w.z, w.w)));
}

__global__ void __launch_bounds__(TILE) gnn_mma(
    const float* __restrict__ x,
    const float* __restrict__ W1, const float* __restrict__ b1,
    const float* __restrict__ W2, const float* __restrict__ b2,
    const float* __restrict__ Wl, const float* __restrict__ bl,
    float* __restrict__ out, int NT)
{
    __shared__ float4 su[TILE + 4];   // su[i] = avg input u of node (base + i - 1)
    __shared__ float4 w1pk[HD];       // {W1[0][k], W1[1][k], W1[2][k], b1[k]}
    __shared__ float4 hdt[HD];        // {b2[c], Wl[c][0], Wl[c][1], Wl[c][2]}

    const int t = threadIdx.x;
    const int l = t & 31;
    const int w = t >> 5;
    const int lq  = l >> 2;   // l/4
    const int lr  = l & 3;    // l%4
    const int c   = (w << 5) + lq;   // base row of this thread's fragments

    if (t < HD) {
        float4 v; v.x = W1[t]; v.y = W1[HD + t]; v.z = W1[2 * HD + t]; v.w = b1[t];
        w1pk[t] = v;
    } else {
        int cc = t - HD;
        float4 h; h.x = b2[cc]; h.y = Wl[3 * cc + 0]; h.z = Wl[3 * cc + 1]; h.w = Wl[3 * cc + 2];
        hdt[cc] = h;
    }

    // ---- W2 -> per-thread B fragments (tf32, rna-rounded), held for the whole kernel
    uint32_t breg[8][8][2];
    #pragma unroll
    for (int kb = 0; kb < 8; kb++)
        #pragma unroll
        for (int nb = 0; nb < 8; nb++)
            #pragma unroll
            for (int j = 0; j < 2; j++) {
                int k = kb * 8 + lr + 4 * j;
                int n = nb * 8 + lq;
                breg[kb][nb][j] = f2tf32(W2[k * HD + n]);
            }

    const float bl0 = bl[0], bl1 = bl[1], bl2 = bl[2];

    for (int tile = blockIdx.x; tile < NT; tile += gridDim.x) {
        const int base = tile * TILE;

        // ---- stage averaged inputs: su[t+1] = 0.5*(x[base+t] + x[prev])
        __syncthreads();   // prior tile readers done
        {
            int node = base + t;
            int p = prev_node(node);
            float4 v;
            v.x = 0.5f * (x[3*node+0] + x[3*p+0]);
            v.y = 0.5f * (x[3*node+1] + x[3*p+1]);
            v.z = 0.5f * (x[3*node+2] + x[3*p+2]);
            v.w = 0.0f;
            su[t + 1] = v;
            if (t == 0) {
                int n0 = p, p0 = prev_node(p);
                float4 h;
                h.x = 0.5f * (x[3*n0+0] + x[3*p0+0]);
                h.y = 0.5f * (x[3*n0+1] + x[3*p0+1]);
                h.z = 0.5f * (x[3*n0+2] + x[3*p0+2]);
                h.w = 0.0f;
                su[0] = h;
            }
        }
        __syncthreads();

        // hoist the 8 u-vectors this thread needs (rows c+{0,8,16,24}, cur & prev)
        float4 up[4], uc[4];
        #pragma unroll
        for (int i = 0; i < 4; i++) {
            int r = c + 8 * i;
            up[i] = su[r];        // u of node r-1 (prev)
            uc[i] = su[r + 1];    // u of node r   (cur)
        }

        // ---- accumulators
        float dacc[2][8][4];
        #pragma unroll
        for (int mb = 0; mb < 2; mb++)
            #pragma unroll
            for (int nb = 0; nb < 8; nb++)
                #pragma unroll
                for (int j = 0; j < 4; j++) dacc[mb][nb][j] = 0.0f;

        // ---- k-loop: build A fragments on the fly, mma into D
        #pragma unroll
        for (int kb = 0; kb < 8; kb++) {
            float4 wA = w1pk[kb * 8 + lr];        // k = kb*8 + l%4
            float4 wB = w1pk[kb * 8 + lr + 4];    // k + 4
            #pragma unroll
            for (int mb = 0; mb < 2; mb++) {
                uint32_t afr[4];
                #pragma unroll
                for (int rr = 0; rr < 2; rr++) {
                    int ui = 2 * mb + rr;         // row offset {0,8,16,24}
                    float ycA = fmaxf(dot3(uc[ui], wA), 0.0f);
                    float ypA = fmaxf(dot3(up[ui], wA), 0.0f);
                    afr[rr]     = f2tf32(0.5f * (ycA + ypA));
                    float ycB = fmaxf(dot3(uc[ui], wB), 0.0f);
                    float ypB = fmaxf(dot3(up[ui], wB), 0.0f);
                    afr[rr + 2] = f2tf32(0.5f * (ycB + ypB));
                }
                #pragma unroll
                for (int nb = 0; nb < 8; nb++)
                    mma_tf32(dacc[mb][nb], afr, breg[kb][nb]);
            }
        }

        // ---- epilogue: relu(D + b2) @ Wl, reduce over quad lanes, store
        float o[4][3];
        #pragma unroll
        for (int i = 0; i < 4; i++) { o[i][0] = 0.f; o[i][1] = 0.f; o[i][2] = 0.f; }

        #pragma unroll
        for (int mb = 0; mb < 2; mb++)
            #pragma unroll
            for (int nb = 0; nb < 8; nb++) {
                float4 h0 = hdt[nb * 8 + 2 * lr];
                float4 h1 = hdt[nb * 8 + 2 * lr + 1];
                float y;
                y = fmaxf(dacc[mb][nb][0] + h0.x, 0.0f);
                o[2*mb][0] = fmaf(y, h0.y, o[2*mb][0]);
                o[2*mb][1] = fmaf(y, h0.z, o[2*mb][1]);
                o[2*mb][2] = fmaf(y, h0.w, o[2*mb][2]);
                y = fmaxf(dacc[mb][nb][1] + h1.x, 0.0f);
                o[2*mb][0] = fmaf(y, h1.y, o[2*mb][0]);
                o[2*mb][1] = fmaf(y, h1.z, o[2*mb][1]);
                o[2*mb][2] = fmaf(y, h1.w, o[2*mb][2]);
                y = fmaxf(dacc[mb][nb][2] + h0.x, 0.0f);
                o[2*mb+1][0] = fmaf(y, h0.y, o[2*mb+1][0]);
                o[2*mb+1][1] = fmaf(y, h0.z, o[2*mb+1][1]);
                o[2*mb+1][2] = fmaf(y, h0.w, o[2*mb+1][2]);
                y = fmaxf(dacc[mb][nb][3] + h1.x, 0.0f);
                o[2*mb+1][0] = fmaf(y, h1.y, o[2*mb+1][0]);
                o[2*mb+1][1] = fmaf(y, h1.z, o[2*mb+1][1]);
                o[2*mb+1][2] = fmaf(y, h1.w, o[2*mb+1][2]);
            }

        #pragma unroll
        for (int i = 0; i < 4; i++)
            #pragma unroll
            for (int cc = 0; cc < 3; cc++) {
                float v = o[i][cc];
                v += __shfl_xor_sync(0xffffffffu, v, 1);
                v += __shfl_xor_sync(0xffffffffu, v, 2);
                o[i][cc] = v;
            }

        if (lr == 0) {
            #pragma unroll
            for (int i = 0; i < 4; i++) {
                int node = base + c + 8 * i;
                out[3*node+0] = o[i][0] + bl0;
                out[3*node+1] = o[i][1] + bl1;
                out[3*node+2] = o[i][2] + bl2;
            }
        }
    }
}

extern "C" void kernel_launch(void* const* d_in, const int* in_sizes, int n_in,
                              void* d_out, int out_size) {
    // metadata order: node_index, edge_index, W1, b1, W2, b2, Wl, bl
    const float* x  = (const float*)d_in[0];
    const float* W1 = (const float*)d_in[2];
    const float* b1 = (const float*)d_in[3];
    const float* W2 = (const float*)d_in[4];
    const float* b2 = (const float*)d_in[5];
    const float* Wl = (const float*)d_in[6];
    const float* bl = (const float*)d_in[7];
    float* out = (float*)d_out;

    int N  = in_sizes[0] / 3;
    int NT = N / TILE;
    int grid = 2 * 148;
    if (grid > NT) grid = NT;

    gnn_mma<<<grid, TILE>>>(x, W1, b1, W2, b2, Wl, bl, out, NT);
}